// round 6
// baseline (speedup 1.0000x reference)
#include <cuda_runtime.h>
#include <math.h>

#define Bc 256
#define Vc 4096
#define Kc 64
#define MINIf 1e-6f

#define VK (Vc*Kc)             /* 262144 */
#define BK (Bc*Kc)             /* 16384  */
#define OUT_TN 0
#define OUT_TM VK
#define OUT_QZ (VK+BK)
#define OUT_NN (VK+BK+1)
#define OUT_NM (VK+BK+1+VK)

// device scratch
__device__ float g_theta[BK];
__device__ float g_thetaL[BK];
__device__ float g_phi[VK];
__device__ float g_phiL[VK];
__device__ float g_Nacc[VK];
__device__ float g_Macc[BK];
__device__ float g_denom[Kc];
__device__ float g_rho;
__device__ float g_ratio;
__device__ int   g_idxstride;
// completion counters; atomicInc with wrap self-resets to 0 each invocation
__device__ unsigned g_cntN[64];
__device__ unsigned g_cntM[4];

// ---- packed f32x2 helpers (Blackwell FFMA2) --------------------------------
__device__ __forceinline__ void pfma(unsigned long long& acc,
                                     unsigned long long a, unsigned long long b) {
    asm("fma.rn.f32x2 %0, %1, %2, %0;" : "+l"(acc) : "l"(a), "l"(b));
}
__device__ __forceinline__ float psum(unsigned long long v) {
    return __uint_as_float((unsigned)v) + __uint_as_float((unsigned)(v >> 32));
}
__device__ __forceinline__ unsigned long long fpack2(float lo, float hi) {
    unsigned long long r;
    asm("mov.b64 %0, {%1, %2};" : "=l"(r) : "f"(lo), "f"(hi));
    return r;
}
__device__ __forceinline__ void punpack(unsigned long long v, float& lo, float& hi) {
    lo = __uint_as_float((unsigned)v);
    hi = __uint_as_float((unsigned)(v >> 32));
}

// ---------------------------------------------------------------------------
// K1: coalesced per-topic denominator + scalars/probe/entropy-zero.
__global__ void __launch_bounds__(256) k1_denom(
        const float* __restrict__ beta,
        const float* __restrict__ expn,
        const int* __restrict__ iterp,
        const int* __restrict__ cmp,
        const int* __restrict__ bcp,
        const unsigned int* __restrict__ idxw,
        float* __restrict__ out) {
    if (blockIdx.x < 64) {
        __shared__ float red[16][68];
        int t = threadIdx.x;
        int cq = t & 15, r = t >> 4;
        int v0 = blockIdx.x * 64;
        float4 a = make_float4(0.f, 0.f, 0.f, 0.f);
        #pragma unroll
        for (int j = 0; j < 4; ++j) {
            int row = v0 + r + 16 * j;
            float4 b4 = ((const float4*)beta)[row * 16 + cq];
            float4 e4 = ((const float4*)expn)[row * 16 + cq];
            a.x += b4.x + e4.x; a.y += b4.y + e4.y;
            a.z += b4.z + e4.z; a.w += b4.w + e4.w;
        }
        *(float4*)&red[r][cq * 4] = a;
        __syncthreads();
        if (t < 64) {
            float s = 0.f;
            #pragma unroll
            for (int r2 = 0; r2 < 16; ++r2) s += red[r2][t];
            atomicAdd(&g_denom[t], s);
        }
    } else if (threadIdx.x == 0) {
        g_rho   = 1.f / powf((float)(iterp[0] + 5), 0.9f);
        g_ratio = (float)cmp[0] / (float)bcp[0];
        // int64-vs-int32 probe: if int64, odd 32-bit words (high halves) are 0.
        bool allz = true;
        for (int i = 1; i < Bc; i += 2)
            if (idxw[i] != 0u) { allz = false; break; }
        g_idxstride = allz ? 2 : 1;
        out[OUT_QZ] = 0.f;
    }
}

// ---------------------------------------------------------------------------
// K2: phi, phi*log(phi), theta, theta*log(theta); zero accumulators. (MUFU ok)
__global__ void k2_prep(const float* __restrict__ beta,
                        const float* __restrict__ expn,
                        const float* __restrict__ alpha,
                        const float* __restrict__ pi,
                        const float* __restrict__ expm,
                        const unsigned int* __restrict__ idxw) {
    int i = blockIdx.x * 256 + threadIdx.x;
    if (i < VK) {
        int k = i & (Kc - 1);
        float p = __fdividef(beta[i] + expn[i], g_denom[k]);
        g_phi[i]  = p;
        g_phiL[i] = p * __logf(p);
        g_Nacc[i] = 0.f;
    } else if (i < VK + BK) {
        int j = i - VK;
        int b = j >> 6, k = j & 63;
        int d = (int)idxw[b * g_idxstride];
        float th = alpha[k] * pi[d * Kc + k] + expm[d * Kc + k];
        g_theta[j]  = th;
        g_thetaL[j] = th * __logf(th);
        g_Macc[j]   = 0.f;
    }
}

// ---------------------------------------------------------------------------
// K3 fused: per block 64b x 64v tile.
// Phase 1: S/A GEMM + w + entropy. Phase 2: rank-64 GEMMs into Macc/Nacc
// (float4 atomics). Phase 3: last-arriver blocks finalize the outputs
// (epilogue fused via per-tile completion counters; no separate kernel).
__global__ void __launch_bounds__(256, 2)
k3_fused(const int* __restrict__ bow,
         const float* __restrict__ expn,
         const float* __restrict__ expm,
         const unsigned int* __restrict__ idxw,
         float* __restrict__ out) {
    extern __shared__ float sm3[];
    float (*th)[68]  = (float(*)[68])(sm3);
    float (*thL)[68] = (float(*)[68])(sm3 + 64 * 68);   // becomes Wt in phase 2
    float (*ph)[68]  = (float(*)[68])(sm3 + 128 * 68);
    float (*phL)[68] = (float(*)[68])(sm3 + 192 * 68);
    float (*Wt)[68]  = thL;

    int t = threadIdx.x;
    int v0 = blockIdx.x * 64;
    int b0 = blockIdx.y * 64;

    int tv = t & 15;       // v_local = tv + 16*vi
    int tb = t >> 4;       // b_local = tb + 16*bi

    // hoist the scattered bow loads above the FMA mainloop (latency hidden)
    int cnt[4][4];
    #pragma unroll
    for (int bi = 0; bi < 4; ++bi)
        #pragma unroll
        for (int vi = 0; vi < 4; ++vi)
            cnt[bi][vi] = bow[(b0 + tb + 16 * bi) * Vc + v0 + tv + 16 * vi];

    for (int i = t; i < 64 * 16; i += 256) {
        int r = i >> 4, cq = i & 15;
        *(float4*)&th [r][cq * 4] = ((const float4*)g_theta )[(b0 + r) * 16 + cq];
        *(float4*)&thL[r][cq * 4] = ((const float4*)g_thetaL)[(b0 + r) * 16 + cq];
        *(float4*)&ph [r][cq * 4] = ((const float4*)g_phi   )[(v0 + r) * 16 + cq];
        *(float4*)&phL[r][cq * 4] = ((const float4*)g_phiL  )[(v0 + r) * 16 + cq];
    }
    __syncthreads();

    unsigned long long S2[4][4], A2[4][4];
    #pragma unroll
    for (int bi = 0; bi < 4; ++bi)
        #pragma unroll
        for (int vi = 0; vi < 4; ++vi) { S2[bi][vi] = 0ull; A2[bi][vi] = 0ull; }

    #pragma unroll 4
    for (int kq = 0; kq < 16; ++kq) {
        ulonglong2 P[4], Q[4];
        #pragma unroll
        for (int vi = 0; vi < 4; ++vi) {
            P[vi] = *(const ulonglong2*)&ph [tv + 16 * vi][kq * 4];
            Q[vi] = *(const ulonglong2*)&phL[tv + 16 * vi][kq * 4];
        }
        #pragma unroll
        for (int bi = 0; bi < 4; ++bi) {
            ulonglong2 T = *(const ulonglong2*)&th [tb + 16 * bi][kq * 4];
            ulonglong2 L = *(const ulonglong2*)&thL[tb + 16 * bi][kq * 4];
            #pragma unroll
            for (int vi = 0; vi < 4; ++vi) {
                pfma(S2[bi][vi], T.x, P[vi].x);
                pfma(S2[bi][vi], T.y, P[vi].y);
                pfma(A2[bi][vi], L.x, P[vi].x);
                pfma(A2[bi][vi], L.y, P[vi].y);
                pfma(A2[bi][vi], T.x, Q[vi].x);
                pfma(A2[bi][vi], T.y, Q[vi].y);
            }
        }
    }

    // epilogue of phase 1: w, entropy (MUFU rcp/log — hidden under FMA issue)
    float wv[4][4];
    float ent = 0.f;
    #pragma unroll
    for (int bi = 0; bi < 4; ++bi) {
        #pragma unroll
        for (int vi = 0; vi < 4; ++vi) {
            float S = psum(S2[bi][vi]);
            float A = psum(A2[bi][vi]);
            float sp = S + MINIf;
            float r  = __fdividef(1.f, sp);
            int c = cnt[bi][vi];
            wv[bi][vi] = (float)c * r;
            if (c > 0)
                ent += (A - S * __logf(sp)) * r;
        }
    }

    // block entropy reduction
    #pragma unroll
    for (int o = 16; o; o >>= 1)
        ent += __shfl_xor_sync(0xFFFFFFFFu, ent, o);
    __shared__ float ered[8];
    if ((t & 31) == 0) ered[t >> 5] = ent;

    __syncthreads();   // all thL reads done; ered visible
    if (t == 0) {
        float s = 0.f;
        #pragma unroll
        for (int w = 0; w < 8; ++w) s += ered[w];
        atomicAdd(&out[OUT_QZ], s);
    }

    // stage W into smem (overwrites thL)
    #pragma unroll
    for (int bi = 0; bi < 4; ++bi)
        #pragma unroll
        for (int vi = 0; vi < 4; ++vi)
            Wt[tb + 16 * bi][tv + 16 * vi] = wv[bi][vi];
    __syncthreads();

    // ---- phase 2 ----
    int kq2 = t & 15;            // k = kq2*4 .. +3
    int tr  = t >> 4;            // row group: tr + 16*j

    // 2a: Macc[b, k] += sum_c Wt[b_local][c] * ph[c][k]
    {
        unsigned long long acc[4][2];
        #pragma unroll
        for (int j = 0; j < 4; ++j) { acc[j][0] = 0ull; acc[j][1] = 0ull; }
        #pragma unroll 8
        for (int c = 0; c < 64; ++c) {
            ulonglong2 p2 = *(const ulonglong2*)&ph[c][kq2 * 4];
            #pragma unroll
            for (int j = 0; j < 4; ++j) {
                float w = Wt[tr + 16 * j][c];
                unsigned long long w2 = fpack2(w, w);
                pfma(acc[j][0], w2, p2.x);
                pfma(acc[j][1], w2, p2.y);
            }
        }
        #pragma unroll
        for (int j = 0; j < 4; ++j) {
            float4 o4;
            punpack(acc[j][0], o4.x, o4.y);
            punpack(acc[j][1], o4.z, o4.w);
            atomicAdd((float4*)&g_Macc[(b0 + tr + 16 * j) * Kc + kq2 * 4], o4);
        }
    }

    // 2b: Nacc[v, k] += sum_c Wt[c][v_local] * th[c][k]
    {
        unsigned long long acc[4][2];
        #pragma unroll
        for (int j = 0; j < 4; ++j) { acc[j][0] = 0ull; acc[j][1] = 0ull; }
        #pragma unroll 8
        for (int c = 0; c < 64; ++c) {
            ulonglong2 t2 = *(const ulonglong2*)&th[c][kq2 * 4];
            #pragma unroll
            for (int j = 0; j < 4; ++j) {
                float w = Wt[c][tr + 16 * j];
                unsigned long long w2 = fpack2(w, w);
                pfma(acc[j][0], w2, t2.x);
                pfma(acc[j][1], w2, t2.y);
            }
        }
        #pragma unroll
        for (int j = 0; j < 4; ++j) {
            float4 o4;
            punpack(acc[j][0], o4.x, o4.y);
            punpack(acc[j][1], o4.z, o4.w);
            atomicAdd((float4*)&g_Nacc[(v0 + tr + 16 * j) * Kc + kq2 * 4], o4);
        }
    }

    // ---- phase 3: per-tile completion counters + fused epilogue ----
    __shared__ int s_lastN, s_lastM;
    __threadfence();            // order this thread's REDs before counter inc
    __syncthreads();            // all threads' REDs fenced
    if (t == 0) {
        unsigned oldN = atomicInc(&g_cntN[blockIdx.x], 3u);   // wraps 3 -> 0
        unsigned oldM = atomicInc(&g_cntM[blockIdx.y], 63u);  // wraps 63 -> 0
        s_lastN = (oldN == 3u);
        s_lastM = (oldM == 63u);
    }
    __syncthreads();

    if (s_lastN) {
        // finalize temp_exp_n / new_exp_n for v in [v0, v0+64)
        __threadfence();
        float rho = g_rho, omr = 1.f - rho, rr = rho * g_ratio;
        int base4 = v0 * 16;            // float4 index of row v0
        #pragma unroll
        for (int u = 0; u < 4; ++u) {
            int i4 = base4 + u * 256 + t;
            float4 p = ((const float4*)g_phi )[i4];
            float4 n = ((const float4*)g_Nacc)[i4];
            float4 e = ((const float4*)expn  )[i4];
            float4 tn = make_float4(p.x*n.x, p.y*n.y, p.z*n.z, p.w*n.w);
            ((float4*)(out + OUT_TN))[i4] = tn;
            int bb = OUT_NN + i4 * 4;
            out[bb+0] = fmaf(omr, e.x, rr*tn.x);
            out[bb+1] = fmaf(omr, e.y, rr*tn.y);
            out[bb+2] = fmaf(omr, e.z, rr*tn.z);
            out[bb+3] = fmaf(omr, e.w, rr*tn.w);
        }
    }

    if (s_lastM) {
        // finalize temp_exp_m / new_exp_m_batch for b in [b0, b0+64)
        __threadfence();
        float rho = g_rho, omr = 1.f - rho;
        int stride = g_idxstride;
        int base4 = b0 * 16;            // float4 index of row b0
        #pragma unroll
        for (int u = 0; u < 4; ++u) {
            int i4 = base4 + u * 256 + t;
            int j = i4 * 4;
            int b = j >> 6, k = j & 63;
            float4 t4 = ((const float4*)g_theta)[i4];
            float4 m4 = ((const float4*)g_Macc)[i4];
            float4 tm = make_float4(t4.x*m4.x, t4.y*m4.y, t4.z*m4.z, t4.w*m4.w);
            ((float4*)(out + OUT_TM))[i4] = tm;
            int d = (int)idxw[b * stride];
            float4 em = ((const float4*)expm)[d * 16 + (k >> 2)];
            int bb = OUT_NM + j;
            out[bb+0] = fmaf(omr, em.x, rho*tm.x);
            out[bb+1] = fmaf(omr, em.y, rho*tm.y);
            out[bb+2] = fmaf(omr, em.z, rho*tm.z);
            out[bb+3] = fmaf(omr, em.w, rho*tm.w);
        }
    }
}

// ---------------------------------------------------------------------------
extern "C" void kernel_launch(void* const* d_in, const int* in_sizes, int n_in,
                              void* d_out, int out_size) {
    const int*          bow   = (const int*)d_in[0];
    const unsigned int* idxw  = (const unsigned int*)d_in[1];
    const float*        alpha = (const float*)d_in[2];
    const float*        pi    = (const float*)d_in[3];
    const float*        expm  = (const float*)d_in[4];
    const float*        beta  = (const float*)d_in[5];
    const float*        expn  = (const float*)d_in[6];
    const int*          iterp = (const int*)d_in[7];
    const int*          cmp   = (const int*)d_in[8];
    const int*          bcp   = (const int*)d_in[9];
    float* out = (float*)d_out;

    static int smem_set = 0;
    const int k3_smem = 256 * 68 * 4;  // 69632 bytes
    if (!smem_set) {
        cudaFuncSetAttribute(k3_fused, cudaFuncAttributeMaxDynamicSharedMemorySize, k3_smem);
        smem_set = 1;
    }

    void* denom_ptr = nullptr;
    cudaGetSymbolAddress(&denom_ptr, g_denom);
    cudaMemsetAsync(denom_ptr, 0, Kc * sizeof(float));

    k1_denom<<<65, 256>>>(beta, expn, iterp, cmp, bcp, idxw, out);
    k2_prep<<<(VK + BK) / 256, 256>>>(beta, expn, alpha, pi, expm, idxw);
    dim3 g3(Vc / 64, Bc / 64);
    k3_fused<<<g3, 256, k3_smem>>>(bow, expn, expm, idxw, out);
}

// round 7
// speedup vs baseline: 1.1144x; 1.1144x over previous
#include <cuda_runtime.h>
#include <math.h>

#define Bc 256
#define Vc 4096
#define Kc 64
#define MINIf 1e-6f

#define VK (Vc*Kc)             /* 262144 */
#define BK (Bc*Kc)             /* 16384  */
#define OUT_TN 0
#define OUT_TM VK
#define OUT_QZ (VK+BK)
#define OUT_NN (VK+BK+1)
#define OUT_NM (VK+BK+1+VK)

// device scratch
__device__ float g_theta[BK];
__device__ float g_thetaL[BK];
__device__ float g_phi[VK];
__device__ float g_phiL[VK];
__device__ float g_Nacc[VK];
__device__ float g_Macc[BK];
__device__ float g_denom[Kc];
__device__ float g_rho;
__device__ float g_ratio;
__device__ int   g_idxstride;

// ---- packed f32x2 helpers (Blackwell FFMA2) --------------------------------
__device__ __forceinline__ void pfma(unsigned long long& acc,
                                     unsigned long long a, unsigned long long b) {
    asm("fma.rn.f32x2 %0, %1, %2, %0;" : "+l"(acc) : "l"(a), "l"(b));
}
__device__ __forceinline__ float psum(unsigned long long v) {
    return __uint_as_float((unsigned)v) + __uint_as_float((unsigned)(v >> 32));
}
__device__ __forceinline__ unsigned long long fpack2(float lo, float hi) {
    unsigned long long r;
    asm("mov.b64 %0, {%1, %2};" : "=l"(r) : "f"(lo), "f"(hi));
    return r;
}
__device__ __forceinline__ void punpack(unsigned long long v, float& lo, float& hi) {
    lo = __uint_as_float((unsigned)v);
    hi = __uint_as_float((unsigned)(v >> 32));
}

// ---------------------------------------------------------------------------
// K1: per-topic denominator. 128 data blocks x 32 v-rows; 4 independent
// LDG.128 per thread issued up front (MLP), smem transpose, spread atomics.
__global__ void __launch_bounds__(256) k1_denom(
        const float* __restrict__ beta,
        const float* __restrict__ expn,
        const int* __restrict__ iterp,
        const int* __restrict__ cmp,
        const int* __restrict__ bcp,
        const unsigned int* __restrict__ idxw,
        float* __restrict__ out) {
    if (blockIdx.x < 128) {
        __shared__ float red[16][68];
        int t = threadIdx.x;
        int cq = t & 15, r = t >> 4;
        int v0 = blockIdx.x * 32;
        // 4 independent loads, all issued before any use
        float4 b0 = ((const float4*)beta)[(v0 + r     ) * 16 + cq];
        float4 b1 = ((const float4*)beta)[(v0 + r + 16) * 16 + cq];
        float4 e0 = ((const float4*)expn)[(v0 + r     ) * 16 + cq];
        float4 e1 = ((const float4*)expn)[(v0 + r + 16) * 16 + cq];
        float4 a;
        a.x = (b0.x + e0.x) + (b1.x + e1.x);
        a.y = (b0.y + e0.y) + (b1.y + e1.y);
        a.z = (b0.z + e0.z) + (b1.z + e1.z);
        a.w = (b0.w + e0.w) + (b1.w + e1.w);
        *(float4*)&red[r][cq * 4] = a;
        __syncthreads();
        if (t < 64) {
            float s = 0.f;
            #pragma unroll
            for (int r2 = 0; r2 < 16; ++r2) s += red[r2][t];
            atomicAdd(&g_denom[t], s);
        }
    } else if (threadIdx.x == 0) {
        g_rho   = 1.f / powf((float)(iterp[0] + 5), 0.9f);
        g_ratio = (float)cmp[0] / (float)bcp[0];
        // int64-vs-int32 probe: if int64, odd 32-bit words (high halves) are 0.
        bool allz = true;
        for (int i = 1; i < Bc; i += 2)
            if (idxw[i] != 0u) { allz = false; break; }
        g_idxstride = allz ? 2 : 1;
        out[OUT_QZ] = 0.f;
    }
}

// ---------------------------------------------------------------------------
// K2: float4-vectorized phi/phiL/theta/thetaL + accumulator zeroing.
__global__ void __launch_bounds__(256) k2_prep(
        const float* __restrict__ beta,
        const float* __restrict__ expn,
        const float* __restrict__ alpha,
        const float* __restrict__ pi,
        const float* __restrict__ expm,
        const unsigned int* __restrict__ idxw) {
    int i4 = blockIdx.x * 256 + threadIdx.x;
    const float4 z4 = make_float4(0.f, 0.f, 0.f, 0.f);
    if (i4 < VK / 4) {
        int k4 = i4 & 15;
        float4 b = ((const float4*)beta)[i4];
        float4 e = ((const float4*)expn)[i4];
        float4 dn = ((const float4*)g_denom)[k4];
        float4 p;
        p.x = __fdividef(b.x + e.x, dn.x);
        p.y = __fdividef(b.y + e.y, dn.y);
        p.z = __fdividef(b.z + e.z, dn.z);
        p.w = __fdividef(b.w + e.w, dn.w);
        float4 pl;
        pl.x = p.x * __logf(p.x);
        pl.y = p.y * __logf(p.y);
        pl.z = p.z * __logf(p.z);
        pl.w = p.w * __logf(p.w);
        ((float4*)g_phi )[i4] = p;
        ((float4*)g_phiL)[i4] = pl;
        ((float4*)g_Nacc)[i4] = z4;
    } else {
        int j4 = i4 - VK / 4;           // 0..4095
        int b = j4 >> 4, k4 = j4 & 15;
        int d = (int)idxw[b * g_idxstride];
        float4 al = ((const float4*)alpha)[k4];
        float4 pp = ((const float4*)pi  )[d * 16 + k4];
        float4 em = ((const float4*)expm)[d * 16 + k4];
        float4 th;
        th.x = fmaf(al.x, pp.x, em.x);
        th.y = fmaf(al.y, pp.y, em.y);
        th.z = fmaf(al.z, pp.z, em.z);
        th.w = fmaf(al.w, pp.w, em.w);
        float4 tl;
        tl.x = th.x * __logf(th.x);
        tl.y = th.y * __logf(th.y);
        tl.z = th.z * __logf(th.z);
        tl.w = th.w * __logf(th.w);
        ((float4*)g_theta )[j4] = th;
        ((float4*)g_thetaL)[j4] = tl;
        ((float4*)g_Macc  )[j4] = z4;
    }
}

// ---------------------------------------------------------------------------
// K3 fused: per block 64b x 64v tile. Phase 1 S/A GEMM + w/entropy;
// Phase 2 two rank-64 GEMMs into Macc/Nacc with float4 atomics.
__global__ void __launch_bounds__(256, 2)
k3_fused(const int* __restrict__ bow, float* __restrict__ out) {
    extern __shared__ float sm3[];
    float (*th)[68]  = (float(*)[68])(sm3);
    float (*thL)[68] = (float(*)[68])(sm3 + 64 * 68);   // becomes Wt in phase 2
    float (*ph)[68]  = (float(*)[68])(sm3 + 128 * 68);
    float (*phL)[68] = (float(*)[68])(sm3 + 192 * 68);
    float (*Wt)[68]  = thL;

    int t = threadIdx.x;
    int v0 = blockIdx.x * 64;
    int b0 = blockIdx.y * 64;

    int tv = t & 15;       // v_local = tv + 16*vi
    int tb = t >> 4;       // b_local = tb + 16*bi

    // hoist the scattered bow loads above the FMA mainloop (latency hidden)
    int cnt[4][4];
    #pragma unroll
    for (int bi = 0; bi < 4; ++bi)
        #pragma unroll
        for (int vi = 0; vi < 4; ++vi)
            cnt[bi][vi] = bow[(b0 + tb + 16 * bi) * Vc + v0 + tv + 16 * vi];

    for (int i = t; i < 64 * 16; i += 256) {
        int r = i >> 4, cq = i & 15;
        *(float4*)&th [r][cq * 4] = ((const float4*)g_theta )[(b0 + r) * 16 + cq];
        *(float4*)&thL[r][cq * 4] = ((const float4*)g_thetaL)[(b0 + r) * 16 + cq];
        *(float4*)&ph [r][cq * 4] = ((const float4*)g_phi   )[(v0 + r) * 16 + cq];
        *(float4*)&phL[r][cq * 4] = ((const float4*)g_phiL  )[(v0 + r) * 16 + cq];
    }
    __syncthreads();

    unsigned long long S2[4][4], A2[4][4];
    #pragma unroll
    for (int bi = 0; bi < 4; ++bi)
        #pragma unroll
        for (int vi = 0; vi < 4; ++vi) { S2[bi][vi] = 0ull; A2[bi][vi] = 0ull; }

    #pragma unroll 4
    for (int kq = 0; kq < 16; ++kq) {
        ulonglong2 P[4], Q[4];
        #pragma unroll
        for (int vi = 0; vi < 4; ++vi) {
            P[vi] = *(const ulonglong2*)&ph [tv + 16 * vi][kq * 4];
            Q[vi] = *(const ulonglong2*)&phL[tv + 16 * vi][kq * 4];
        }
        #pragma unroll
        for (int bi = 0; bi < 4; ++bi) {
            ulonglong2 T = *(const ulonglong2*)&th [tb + 16 * bi][kq * 4];
            ulonglong2 L = *(const ulonglong2*)&thL[tb + 16 * bi][kq * 4];
            #pragma unroll
            for (int vi = 0; vi < 4; ++vi) {
                pfma(S2[bi][vi], T.x, P[vi].x);
                pfma(S2[bi][vi], T.y, P[vi].y);
                pfma(A2[bi][vi], L.x, P[vi].x);
                pfma(A2[bi][vi], L.y, P[vi].y);
                pfma(A2[bi][vi], T.x, Q[vi].x);
                pfma(A2[bi][vi], T.y, Q[vi].y);
            }
        }
    }

    // epilogue of phase 1: w, entropy (MUFU rcp/log — hidden under FMA issue)
    float wv[4][4];
    float ent = 0.f;
    #pragma unroll
    for (int bi = 0; bi < 4; ++bi) {
        #pragma unroll
        for (int vi = 0; vi < 4; ++vi) {
            float S = psum(S2[bi][vi]);
            float A = psum(A2[bi][vi]);
            float sp = S + MINIf;
            float r  = __fdividef(1.f, sp);
            int c = cnt[bi][vi];
            wv[bi][vi] = (float)c * r;
            if (c > 0)
                ent += (A - S * __logf(sp)) * r;
        }
    }

    // block entropy reduction
    #pragma unroll
    for (int o = 16; o; o >>= 1)
        ent += __shfl_xor_sync(0xFFFFFFFFu, ent, o);
    __shared__ float ered[8];
    if ((t & 31) == 0) ered[t >> 5] = ent;

    __syncthreads();   // all thL reads done; ered visible
    if (t == 0) {
        float s = 0.f;
        #pragma unroll
        for (int w = 0; w < 8; ++w) s += ered[w];
        atomicAdd(&out[OUT_QZ], s);
    }

    // stage W into smem (overwrites thL)
    #pragma unroll
    for (int bi = 0; bi < 4; ++bi)
        #pragma unroll
        for (int vi = 0; vi < 4; ++vi)
            Wt[tb + 16 * bi][tv + 16 * vi] = wv[bi][vi];
    __syncthreads();

    // ---- phase 2 ----
    int kq2 = t & 15;            // k = kq2*4 .. +3
    int tr  = t >> 4;            // row group: tr + 16*j

    // 2a: Macc[b, k] += sum_c Wt[b_local][c] * ph[c][k]
    {
        unsigned long long acc[4][2];
        #pragma unroll
        for (int j = 0; j < 4; ++j) { acc[j][0] = 0ull; acc[j][1] = 0ull; }
        #pragma unroll 8
        for (int c = 0; c < 64; ++c) {
            ulonglong2 p2 = *(const ulonglong2*)&ph[c][kq2 * 4];
            #pragma unroll
            for (int j = 0; j < 4; ++j) {
                float w = Wt[tr + 16 * j][c];
                unsigned long long w2 = fpack2(w, w);
                pfma(acc[j][0], w2, p2.x);
                pfma(acc[j][1], w2, p2.y);
            }
        }
        #pragma unroll
        for (int j = 0; j < 4; ++j) {
            float4 o4;
            punpack(acc[j][0], o4.x, o4.y);
            punpack(acc[j][1], o4.z, o4.w);
            atomicAdd((float4*)&g_Macc[(b0 + tr + 16 * j) * Kc + kq2 * 4], o4);
        }
    }

    // 2b: Nacc[v, k] += sum_c Wt[c][v_local] * th[c][k]
    {
        unsigned long long acc[4][2];
        #pragma unroll
        for (int j = 0; j < 4; ++j) { acc[j][0] = 0ull; acc[j][1] = 0ull; }
        #pragma unroll 8
        for (int c = 0; c < 64; ++c) {
            ulonglong2 t2 = *(const ulonglong2*)&th[c][kq2 * 4];
            #pragma unroll
            for (int j = 0; j < 4; ++j) {
                float w = Wt[c][tr + 16 * j];
                unsigned long long w2 = fpack2(w, w);
                pfma(acc[j][0], w2, t2.x);
                pfma(acc[j][1], w2, t2.y);
            }
        }
        #pragma unroll
        for (int j = 0; j < 4; ++j) {
            float4 o4;
            punpack(acc[j][0], o4.x, o4.y);
            punpack(acc[j][1], o4.z, o4.w);
            atomicAdd((float4*)&g_Nacc[(v0 + tr + 16 * j) * Kc + kq2 * 4], o4);
        }
    }
}

// ---------------------------------------------------------------------------
// K6: epilogue, 2 independent float4 units per thread for MLP; loads first.
__global__ void __launch_bounds__(256) k6_epi(
        const float* __restrict__ expn,
        const float* __restrict__ expm,
        const unsigned int* __restrict__ idxw,
        float* __restrict__ out) {
    float rho = g_rho, omr = 1.f - rho, rr = rho * g_ratio;
    int t = threadIdx.x;
    if (blockIdx.x < 128) {
        int i0 = blockIdx.x * 512 + t;        // unit 0
        int i1 = i0 + 256;                     // unit 1
        float4 p0 = ((const float4*)g_phi )[i0];
        float4 p1 = ((const float4*)g_phi )[i1];
        float4 n0 = ((const float4*)g_Nacc)[i0];
        float4 n1 = ((const float4*)g_Nacc)[i1];
        float4 e0 = ((const float4*)expn  )[i0];
        float4 e1 = ((const float4*)expn  )[i1];
        float4 tn0 = make_float4(p0.x*n0.x, p0.y*n0.y, p0.z*n0.z, p0.w*n0.w);
        float4 tn1 = make_float4(p1.x*n1.x, p1.y*n1.y, p1.z*n1.z, p1.w*n1.w);
        ((float4*)(out + OUT_TN))[i0] = tn0;
        ((float4*)(out + OUT_TN))[i1] = tn1;
        int b0 = OUT_NN + i0 * 4;
        out[b0+0] = fmaf(omr, e0.x, rr*tn0.x);
        out[b0+1] = fmaf(omr, e0.y, rr*tn0.y);
        out[b0+2] = fmaf(omr, e0.z, rr*tn0.z);
        out[b0+3] = fmaf(omr, e0.w, rr*tn0.w);
        int b1 = OUT_NN + i1 * 4;
        out[b1+0] = fmaf(omr, e1.x, rr*tn1.x);
        out[b1+1] = fmaf(omr, e1.y, rr*tn1.y);
        out[b1+2] = fmaf(omr, e1.z, rr*tn1.z);
        out[b1+3] = fmaf(omr, e1.w, rr*tn1.w);
    } else {
        int i0 = (blockIdx.x - 128) * 512 + t;     // 0..4095 (BK/4) in 2 units
        int i1 = i0 + 256;
        int j0 = i0 * 4, j1 = i1 * 4;
        int d0 = (int)idxw[(j0 >> 6) * g_idxstride];
        int d1 = (int)idxw[(j1 >> 6) * g_idxstride];
        float4 t0 = ((const float4*)g_theta)[i0];
        float4 t1 = ((const float4*)g_theta)[i1];
        float4 m0 = ((const float4*)g_Macc)[i0];
        float4 m1 = ((const float4*)g_Macc)[i1];
        float4 em0 = ((const float4*)expm)[d0 * 16 + ((j0 & 63) >> 2)];
        float4 em1 = ((const float4*)expm)[d1 * 16 + ((j1 & 63) >> 2)];
        float4 tm0 = make_float4(t0.x*m0.x, t0.y*m0.y, t0.z*m0.z, t0.w*m0.w);
        float4 tm1 = make_float4(t1.x*m1.x, t1.y*m1.y, t1.z*m1.z, t1.w*m1.w);
        ((float4*)(out + OUT_TM))[i0] = tm0;
        ((float4*)(out + OUT_TM))[i1] = tm1;
        int b0 = OUT_NM + j0;
        out[b0+0] = fmaf(omr, em0.x, rho*tm0.x);
        out[b0+1] = fmaf(omr, em0.y, rho*tm0.y);
        out[b0+2] = fmaf(omr, em0.z, rho*tm0.z);
        out[b0+3] = fmaf(omr, em0.w, rho*tm0.w);
        int b1 = OUT_NM + j1;
        out[b1+0] = fmaf(omr, em1.x, rho*tm1.x);
        out[b1+1] = fmaf(omr, em1.y, rho*tm1.y);
        out[b1+2] = fmaf(omr, em1.z, rho*tm1.z);
        out[b1+3] = fmaf(omr, em1.w, rho*tm1.w);
    }
}

// ---------------------------------------------------------------------------
extern "C" void kernel_launch(void* const* d_in, const int* in_sizes, int n_in,
                              void* d_out, int out_size) {
    const int*          bow   = (const int*)d_in[0];
    const unsigned int* idxw  = (const unsigned int*)d_in[1];
    const float*        alpha = (const float*)d_in[2];
    const float*        pi    = (const float*)d_in[3];
    const float*        expm  = (const float*)d_in[4];
    const float*        beta  = (const float*)d_in[5];
    const float*        expn  = (const float*)d_in[6];
    const int*          iterp = (const int*)d_in[7];
    const int*          cmp   = (const int*)d_in[8];
    const int*          bcp   = (const int*)d_in[9];
    float* out = (float*)d_out;

    static int smem_set = 0;
    const int k3_smem = 256 * 68 * 4;  // 69632 bytes
    if (!smem_set) {
        cudaFuncSetAttribute(k3_fused, cudaFuncAttributeMaxDynamicSharedMemorySize, k3_smem);
        smem_set = 1;
    }

    void* denom_ptr = nullptr;
    cudaGetSymbolAddress(&denom_ptr, g_denom);
    cudaMemsetAsync(denom_ptr, 0, Kc * sizeof(float));

    k1_denom<<<129, 256>>>(beta, expn, iterp, cmp, bcp, idxw, out);
    k2_prep<<<(VK + BK) / 1024, 256>>>(beta, expn, alpha, pi, expm, idxw);
    dim3 g3(Vc / 64, Bc / 64);
    k3_fused<<<g3, 256, k3_smem>>>(bow, out);
    k6_epi<<<128 + 8, 256>>>(expn, expm, idxw, out);
}